// round 10
// baseline (speedup 1.0000x reference)
#include <cuda_runtime.h>

// ALIF forward: x_seq [T, n_flat] -> spikes [T, n_flat]. HBM-bound streaming
// recurrence (536 MB traffic, zero reuse). R10 = R9 structure (interleaved
// one-LDG-per-step prefetch, float2, ping-pong) with U: 16 -> 32 so
// outstanding LDGs per warp ride the ~55 per-warp LSU cap (max MLP).
//  - float2: 2 neuron columns/thread, 2 independent recurrence chains.
//  - 32768 threads, block=32 -> 1024 CTAs -> 6.92/SM balance (max 7).
//  - regs ~230 (< 255, no spill): 2x32x2 buffer regs + state.

static constexpr int T_STEPS = 1024;
static constexpr int U = 32;         // time steps per group

__global__ __launch_bounds__(32)
void ALIF_24309514895931_kernel(
    const float2* __restrict__ x,     // [T, n2]
    const float2* __restrict__ v0,    // [n2]
    const float2* __restrict__ a0,    // [n2]
    const float* __restrict__ p_decay_v,
    const float* __restrict__ p_decay_a,
    const float* __restrict__ p_threshold,
    const float* __restrict__ p_beta,
    float2* __restrict__ out,         // [T, n2]
    int n2)                           // n_flat / 2
{
    const int i = blockIdx.x * blockDim.x + threadIdx.x;
    if (i >= n2) return;

    const float dv   = *p_decay_v;
    const float da   = *p_decay_a;
    const float thr  = *p_threshold;
    const float beta = *p_beta;

    float2 v = v0[i];
    float2 a = a0[i];

    const float2* xp = x + i;
    float2*       op = out + i;
    const int stride = n2;            // max index T*n2 = 33.5M -> 32-bit safe

    float2 bufA[U], bufB[U];

    // Prologue: A <- group 0, B <- group 1 (bursts; nothing to overlap yet).
    #pragma unroll
    for (int u = 0; u < U; u++) bufA[u] = xp[u * stride];
    #pragma unroll
    for (int u = 0; u < U; u++) bufB[u] = xp[(U + u) * stride];

    // Consume CUR (group tcur); per step also issue one prefetch LDG for
    // group tcur+2U into the slot just freed.
#define ALIF_STAGE(tcur, CUR, DO_PREFETCH)                                  \
    {                                                                       \
        const int obase = (tcur) * stride;                                  \
        const int pbase = ((tcur) + 2 * U) * stride;                        \
        _Pragma("unroll")                                                   \
        for (int u = 0; u < U; u++) {                                       \
            float2 xv = CUR[u];                                             \
            if (DO_PREFETCH)                                                \
                CUR[u] = xp[pbase + u * stride];                            \
            float2 s;                                                       \
            v.x = fmaf(dv, v.x, xv.x);                                      \
            v.y = fmaf(dv, v.y, xv.y);                                      \
            float thx = fmaf(beta, a.x, thr);                               \
            float thy = fmaf(beta, a.y, thr);                               \
            s.x = (v.x > thx) ? 1.0f : 0.0f;                                \
            s.y = (v.y > thy) ? 1.0f : 0.0f;                                \
            v.x = fmaf(-s.x, thx, v.x);                                     \
            v.y = fmaf(-s.y, thy, v.y);                                     \
            a.x = fmaf(da, a.x, s.x);                                       \
            a.y = fmaf(da, a.y, s.y);                                       \
            op[obase + u * stride] = s;                                     \
        }                                                                   \
    }

    // 32 groups of U=32. Main loop: groups 0..29 with prefetch of t+2U;
    // last two groups (t = 960, 1008-? -> 960 and 992) consume only.
    #pragma unroll 1
    for (int t = 0; t < T_STEPS - 2 * U; t += 2 * U) {
        ALIF_STAGE(t,     bufA, true);    // consume A(t),   A <- t+2U
        ALIF_STAGE(t + U, bufB, true);    // consume B(t+U), B <- t+3U
    }
    ALIF_STAGE(T_STEPS - 2 * U, bufA, false);
    ALIF_STAGE(T_STEPS - U,     bufB, false);
#undef ALIF_STAGE
}

extern "C" void kernel_launch(void* const* d_in, const int* in_sizes, int n_in,
                              void* d_out, int out_size) {
    const float* x     = (const float*)d_in[0];
    const float* v0    = (const float*)d_in[1];
    const float* a0    = (const float*)d_in[2];
    const float* dv    = (const float*)d_in[3];
    const float* da    = (const float*)d_in[4];
    const float* thr   = (const float*)d_in[5];
    const float* beta  = (const float*)d_in[6];
    // d_in[7] = alpha: unused in forward pass.

    const int n_flat = in_sizes[1];
    const int n2 = n_flat / 2;        // n_flat = 65536, even

    dim3 block(32);
    dim3 grid((n2 + 31) / 32);
    ALIF_24309514895931_kernel<<<grid, block>>>(
        (const float2*)x, (const float2*)v0, (const float2*)a0,
        dv, da, thr, beta, (float2*)d_out, n2);
}

// round 12
// speedup vs baseline: 1.0573x; 1.0573x over previous
#include <cuda_runtime.h>

// ALIF forward: x_seq [T, n_flat] -> spikes [T, n_flat]. HBM-bound streaming
// recurrence (536 MB traffic, zero reuse). R11 = R9's interleaved
// one-LDG-per-step prefetch ping-pong, but SCALAR (1 column/thread):
//  - 65536 threads, block=64 -> 1024 CTAs -> 6.92 CTAs/SM = 13.8 warps/SM
//    (2x R9's warp count) for better scoreboard-stall coverage.
//  - U=16, chip-wide in-flight stays ~4 MB; regs ~60 -> zero spill risk.

static constexpr int T_STEPS = 1024;
static constexpr int U = 16;         // time steps per group

__global__ __launch_bounds__(64)
void ALIF_24309514895931_kernel(
    const float* __restrict__ x,      // [T, n_flat]
    const float* __restrict__ v0,     // [n_flat]
    const float* __restrict__ a0,     // [n_flat]
    const float* __restrict__ p_decay_v,
    const float* __restrict__ p_decay_a,
    const float* __restrict__ p_threshold,
    const float* __restrict__ p_beta,
    float* __restrict__ out,          // [T, n_flat]
    int n_flat)
{
    const int i = blockIdx.x * blockDim.x + threadIdx.x;
    if (i >= n_flat) return;

    const float dv   = *p_decay_v;
    const float da   = *p_decay_a;
    const float thr  = *p_threshold;
    const float beta = *p_beta;

    float v = v0[i];
    float a = a0[i];

    const float* xp = x + i;
    float*       op = out + i;
    const int stride = n_flat;        // max index T*n_flat = 67M -> 32-bit ok

    float bufA[U], bufB[U];

    // Prologue: A <- group 0, B <- group 1.
    #pragma unroll
    for (int u = 0; u < U; u++) bufA[u] = xp[u * stride];
    #pragma unroll
    for (int u = 0; u < U; u++) bufB[u] = xp[(U + u) * stride];

    // Consume CUR (group tcur); per step also issue one prefetch LDG for
    // group tcur+2U into the slot just freed.
#define ALIF_STAGE(tcur, CUR, DO_PREFETCH)                                  \
    {                                                                       \
        const int obase = (tcur) * stride;                                  \
        const int pbase = ((tcur) + 2 * U) * stride;                        \
        _Pragma("unroll")                                                   \
        for (int u = 0; u < U; u++) {                                       \
            float xv = CUR[u];                                              \
            if (DO_PREFETCH)                                                \
                CUR[u] = xp[pbase + u * stride];                            \
            v = fmaf(dv, v, xv);                                            \
            float th = fmaf(beta, a, thr);                                  \
            float s  = (v > th) ? 1.0f : 0.0f;                              \
            v = fmaf(-s, th, v);                                            \
            a = fmaf(da, a, s);                                             \
            op[obase + u * stride] = s;                                     \
        }                                                                   \
    }

    // 64 groups of U=16: groups 0..61 with prefetch, last two consume-only.
    #pragma unroll 1
    for (int t = 0; t < T_STEPS - 2 * U; t += 2 * U) {
        ALIF_STAGE(t,     bufA, true);    // consume A(t),   A <- t+2U
        ALIF_STAGE(t + U, bufB, true);    // consume B(t+U), B <- t+3U
    }
    ALIF_STAGE(T_STEPS - 2 * U, bufA, false);
    ALIF_STAGE(T_STEPS - U,     bufB, false);
#undef ALIF_STAGE
}

extern "C" void kernel_launch(void* const* d_in, const int* in_sizes, int n_in,
                              void* d_out, int out_size) {
    const float* x     = (const float*)d_in[0];
    const float* v0    = (const float*)d_in[1];
    const float* a0    = (const float*)d_in[2];
    const float* dv    = (const float*)d_in[3];
    const float* da    = (const float*)d_in[4];
    const float* thr   = (const float*)d_in[5];
    const float* beta  = (const float*)d_in[6];
    // d_in[7] = alpha: unused in forward pass.

    const int n_flat = in_sizes[1];

    dim3 block(64);
    dim3 grid((n_flat + 63) / 64);
    ALIF_24309514895931_kernel<<<grid, block>>>(
        x, v0, a0, dv, da, thr, beta, (float*)d_out, n_flat);
}

// round 13
// speedup vs baseline: 1.0709x; 1.0128x over previous
#include <cuda_runtime.h>

// ALIF forward: x_seq [T, n_flat] -> spikes [T, n_flat]. HBM-bound streaming
// recurrence (536 MB traffic, zero reuse). R13 = R9 (float2, interleaved
// one-LDG-per-step prefetch, ping-pong U=16, 1024 CTAs x 32) with ONE change:
// stores are batched in runs of 8 STG.64 (spikes staged in registers) so the
// DRAM scheduler sees longer read runs and write runs -> fewer bus
// turnarounds. regs ~180 (< 255, no spill).

static constexpr int T_STEPS = 1024;
static constexpr int U  = 16;        // time steps per group
static constexpr int SB = 8;         // store-batch length

__global__ __launch_bounds__(32)
void ALIF_24309514895931_kernel(
    const float2* __restrict__ x,     // [T, n2]
    const float2* __restrict__ v0,    // [n2]
    const float2* __restrict__ a0,    // [n2]
    const float* __restrict__ p_decay_v,
    const float* __restrict__ p_decay_a,
    const float* __restrict__ p_threshold,
    const float* __restrict__ p_beta,
    float2* __restrict__ out,         // [T, n2]
    int n2)                           // n_flat / 2
{
    const int i = blockIdx.x * blockDim.x + threadIdx.x;
    if (i >= n2) return;

    const float dv   = *p_decay_v;
    const float da   = *p_decay_a;
    const float thr  = *p_threshold;
    const float beta = *p_beta;

    float2 v = v0[i];
    float2 a = a0[i];

    const float2* xp = x + i;
    float2*       op = out + i;
    const int stride = n2;            // max index T*n2 = 33.5M -> 32-bit safe

    float2 bufA[U], bufB[U];

    // Prologue: A <- group 0, B <- group 1.
    #pragma unroll
    for (int u = 0; u < U; u++) bufA[u] = xp[u * stride];
    #pragma unroll
    for (int u = 0; u < U; u++) bufB[u] = xp[(U + u) * stride];

    // Consume CUR (group tcur). Loads (prefetch of group tcur+2U) interleave
    // one-per-step; stores are deferred into sreg[] and emitted in bursts of
    // SB back-to-back STG.64.
#define ALIF_STAGE(tcur, CUR, DO_PREFETCH)                                  \
    {                                                                       \
        const int obase = (tcur) * stride;                                  \
        const int pbase = ((tcur) + 2 * U) * stride;                        \
        _Pragma("unroll")                                                   \
        for (int b = 0; b < U; b += SB) {                                   \
            float2 sreg[SB];                                                \
            _Pragma("unroll")                                               \
            for (int u2 = 0; u2 < SB; u2++) {                               \
                const int u = b + u2;                                       \
                float2 xv = CUR[u];                                         \
                if (DO_PREFETCH)                                            \
                    CUR[u] = xp[pbase + u * stride];                        \
                float2 s;                                                   \
                v.x = fmaf(dv, v.x, xv.x);                                  \
                v.y = fmaf(dv, v.y, xv.y);                                  \
                float thx = fmaf(beta, a.x, thr);                           \
                float thy = fmaf(beta, a.y, thr);                           \
                s.x = (v.x > thx) ? 1.0f : 0.0f;                            \
                s.y = (v.y > thy) ? 1.0f : 0.0f;                            \
                v.x = fmaf(-s.x, thx, v.x);                                 \
                v.y = fmaf(-s.y, thy, v.y);                                 \
                a.x = fmaf(da, a.x, s.x);                                   \
                a.y = fmaf(da, a.y, s.y);                                   \
                sreg[u2] = s;                                               \
            }                                                               \
            _Pragma("unroll")                                               \
            for (int u2 = 0; u2 < SB; u2++)                                 \
                op[obase + (b + u2) * stride] = sreg[u2];                   \
        }                                                                   \
    }

    // 64 groups of U=16: groups 0..61 with prefetch, last two consume-only.
    #pragma unroll 1
    for (int t = 0; t < T_STEPS - 2 * U; t += 2 * U) {
        ALIF_STAGE(t,     bufA, true);    // consume A(t),   A <- t+2U
        ALIF_STAGE(t + U, bufB, true);    // consume B(t+U), B <- t+3U
    }
    ALIF_STAGE(T_STEPS - 2 * U, bufA, false);
    ALIF_STAGE(T_STEPS - U,     bufB, false);
#undef ALIF_STAGE
}

extern "C" void kernel_launch(void* const* d_in, const int* in_sizes, int n_in,
                              void* d_out, int out_size) {
    const float* x     = (const float*)d_in[0];
    const float* v0    = (const float*)d_in[1];
    const float* a0    = (const float*)d_in[2];
    const float* dv    = (const float*)d_in[3];
    const float* da    = (const float*)d_in[4];
    const float* thr   = (const float*)d_in[5];
    const float* beta  = (const float*)d_in[6];
    // d_in[7] = alpha: unused in forward pass.

    const int n_flat = in_sizes[1];
    const int n2 = n_flat / 2;        // n_flat = 65536, even

    dim3 block(32);
    dim3 grid((n2 + 31) / 32);
    ALIF_24309514895931_kernel<<<grid, block>>>(
        (const float2*)x, (const float2*)v0, (const float2*)a0,
        dv, da, thr, beta, (float2*)d_out, n2);
}

// round 14
// speedup vs baseline: 1.0762x; 1.0049x over previous
#include <cuda_runtime.h>

// ALIF forward: x_seq [T, n_flat] -> spikes [T, n_flat]. HBM-bound streaming
// recurrence (536 MB traffic, zero reuse). R14 = R13 with store batch SB
// widened 8 -> 16: all 16 spikes of a group are staged in registers and
// emitted as 16 back-to-back STG.64, maximizing DRAM write-run length.
// Loads remain interleaved one-LDG-per-step (proven R9 cadence).
// regs ~177 (< 255, no spill). 1024 CTAs x 32 -> 6.92 CTAs/SM balance.

static constexpr int T_STEPS = 1024;
static constexpr int U = 16;         // time steps per group = store batch

__global__ __launch_bounds__(32)
void ALIF_24309514895931_kernel(
    const float2* __restrict__ x,     // [T, n2]
    const float2* __restrict__ v0,    // [n2]
    const float2* __restrict__ a0,    // [n2]
    const float* __restrict__ p_decay_v,
    const float* __restrict__ p_decay_a,
    const float* __restrict__ p_threshold,
    const float* __restrict__ p_beta,
    float2* __restrict__ out,         // [T, n2]
    int n2)                           // n_flat / 2
{
    const int i = blockIdx.x * blockDim.x + threadIdx.x;
    if (i >= n2) return;

    const float dv   = *p_decay_v;
    const float da   = *p_decay_a;
    const float thr  = *p_threshold;
    const float beta = *p_beta;

    float2 v = v0[i];
    float2 a = a0[i];

    const float2* xp = x + i;
    float2*       op = out + i;
    const int stride = n2;            // max index T*n2 = 33.5M -> 32-bit safe

    float2 bufA[U], bufB[U];

    // Prologue: A <- group 0, B <- group 1.
    #pragma unroll
    for (int u = 0; u < U; u++) bufA[u] = xp[u * stride];
    #pragma unroll
    for (int u = 0; u < U; u++) bufB[u] = xp[(U + u) * stride];

    // Consume CUR (group tcur): loads (prefetch of group tcur+2U) interleave
    // one-per-step; all U spikes staged in sreg[], then one burst of U
    // back-to-back STG.64.
#define ALIF_STAGE(tcur, CUR, DO_PREFETCH)                                  \
    {                                                                       \
        const int obase = (tcur) * stride;                                  \
        const int pbase = ((tcur) + 2 * U) * stride;                        \
        float2 sreg[U];                                                     \
        _Pragma("unroll")                                                   \
        for (int u = 0; u < U; u++) {                                       \
            float2 xv = CUR[u];                                             \
            if (DO_PREFETCH)                                                \
                CUR[u] = xp[pbase + u * stride];                            \
            float2 s;                                                       \
            v.x = fmaf(dv, v.x, xv.x);                                      \
            v.y = fmaf(dv, v.y, xv.y);                                      \
            float thx = fmaf(beta, a.x, thr);                               \
            float thy = fmaf(beta, a.y, thr);                               \
            s.x = (v.x > thx) ? 1.0f : 0.0f;                                \
            s.y = (v.y > thy) ? 1.0f : 0.0f;                                \
            v.x = fmaf(-s.x, thx, v.x);                                     \
            v.y = fmaf(-s.y, thy, v.y);                                     \
            a.x = fmaf(da, a.x, s.x);                                       \
            a.y = fmaf(da, a.y, s.y);                                       \
            sreg[u] = s;                                                    \
        }                                                                   \
        _Pragma("unroll")                                                   \
        for (int u = 0; u < U; u++)                                         \
            op[obase + u * stride] = sreg[u];                               \
    }

    // 64 groups of U=16: groups 0..61 with prefetch, last two consume-only.
    #pragma unroll 1
    for (int t = 0; t < T_STEPS - 2 * U; t += 2 * U) {
        ALIF_STAGE(t,     bufA, true);    // consume A(t),   A <- t+2U
        ALIF_STAGE(t + U, bufB, true);    // consume B(t+U), B <- t+3U
    }
    ALIF_STAGE(T_STEPS - 2 * U, bufA, false);
    ALIF_STAGE(T_STEPS - U,     bufB, false);
#undef ALIF_STAGE
}

extern "C" void kernel_launch(void* const* d_in, const int* in_sizes, int n_in,
                              void* d_out, int out_size) {
    const float* x     = (const float*)d_in[0];
    const float* v0    = (const float*)d_in[1];
    const float* a0    = (const float*)d_in[2];
    const float* dv    = (const float*)d_in[3];
    const float* da    = (const float*)d_in[4];
    const float* thr   = (const float*)d_in[5];
    const float* beta  = (const float*)d_in[6];
    // d_in[7] = alpha: unused in forward pass.

    const int n_flat = in_sizes[1];
    const int n2 = n_flat / 2;        // n_flat = 65536, even

    dim3 block(32);
    dim3 grid((n2 + 31) / 32);
    ALIF_24309514895931_kernel<<<grid, block>>>(
        (const float2*)x, (const float2*)v0, (const float2*)a0,
        dv, da, thr, beta, (float2*)d_out, n2);
}